// round 1
// baseline (speedup 1.0000x reference)
#include <cuda_runtime.h>
#include <math.h>

#define MODEL_DIM 4096
#define NH 32
#define NG 8
#define HD 128
#define KV_DIM 1024                       // NG*HD
#define QKV_N (MODEL_DIM + 2 * KV_DIM)    // 6144
#define S_LEN 2048

// Scratch (allocation-free rule: __device__ globals)
__device__ float g_qkv[S_LEN * QKV_N];      // [2048, 6144]
__device__ float g_attn[S_LEN * MODEL_DIM]; // [2048, 4096]

// ---------------------------------------------------------------------------
// SGEMM: C[M,N] = A[M,K] @ B[K,N] + bias[N]   (all row-major, fp32)
// 128x128x16 tiles, 256 threads, 8x8 micro-tile per thread
// ---------------------------------------------------------------------------
__global__ __launch_bounds__(256) void sgemm_bias_kernel(
    const float* __restrict__ A, const float* __restrict__ B,
    const float* __restrict__ bias, float* __restrict__ C,
    int M, int N, int K)
{
    const int BM = 128, BN = 128, BK = 16;
    __shared__ float As[16][132];  // transposed A tile, padded
    __shared__ float Bs[16][128];

    int tid = threadIdx.x;
    int tx = tid % 16;
    int ty = tid / 16;
    int bm = blockIdx.y * BM;
    int bn = blockIdx.x * BN;

    float acc[8][8];
#pragma unroll
    for (int i = 0; i < 8; i++)
#pragma unroll
        for (int j = 0; j < 8; j++) acc[i][j] = 0.f;

    for (int k0 = 0; k0 < K; k0 += BK) {
        // Load A tile: 128 rows x 16 cols = 512 float4, 2 per thread; store transposed
#pragma unroll
        for (int l = 0; l < 2; l++) {
            int idx = tid + l * 256;
            int r  = idx / 4;          // 0..127
            int c4 = (idx % 4) * 4;    // 0,4,8,12
            float4 v = *(const float4*)&A[(size_t)(bm + r) * K + k0 + c4];
            As[c4 + 0][r] = v.x;
            As[c4 + 1][r] = v.y;
            As[c4 + 2][r] = v.z;
            As[c4 + 3][r] = v.w;
        }
        // Load B tile: 16 rows x 128 cols = 512 float4, 2 per thread
#pragma unroll
        for (int l = 0; l < 2; l++) {
            int idx = tid + l * 256;
            int r  = idx / 32;         // 0..15
            int c4 = (idx % 32) * 4;
            *(float4*)&Bs[r][c4] = *(const float4*)&B[(size_t)(k0 + r) * N + bn + c4];
        }
        __syncthreads();

#pragma unroll
        for (int kk = 0; kk < BK; kk++) {
            float a[8], b[8];
            *(float4*)&a[0] = *(float4*)&As[kk][ty * 8];
            *(float4*)&a[4] = *(float4*)&As[kk][ty * 8 + 4];
            *(float4*)&b[0] = *(float4*)&Bs[kk][tx * 8];
            *(float4*)&b[4] = *(float4*)&Bs[kk][tx * 8 + 4];
#pragma unroll
            for (int i = 0; i < 8; i++)
#pragma unroll
                for (int j = 0; j < 8; j++)
                    acc[i][j] = fmaf(a[i], b[j], acc[i][j]);
        }
        __syncthreads();
    }

    // Epilogue: add bias, store
#pragma unroll
    for (int i = 0; i < 8; i++) {
        int r = bm + ty * 8 + i;
#pragma unroll
        for (int j = 0; j < 8; j += 4) {
            int c = bn + tx * 8 + j;
            float4 o;
            o.x = acc[i][j + 0] + bias[c + 0];
            o.y = acc[i][j + 1] + bias[c + 1];
            o.z = acc[i][j + 2] + bias[c + 2];
            o.w = acc[i][j + 3] + bias[c + 3];
            *(float4*)&C[(size_t)r * N + c] = o;
        }
    }
}

// ---------------------------------------------------------------------------
// RoPE in-place on Q (32 heads) and K (8 heads). Llama-style:
//   out[d]    = x[d]*cos(a_d) - x[d+64]*sin(a_d)        (d < 64)
//   out[d+64] = x[d+64]*cos(a_d) + x[d]*sin(a_d)
// angle a_d = s * BASE^(-2d/HD). Double-precision angle generation.
// ---------------------------------------------------------------------------
__global__ __launch_bounds__(64) void rope_kernel(float* __restrict__ qkv)
{
    int s = blockIdx.x;        // 0..2047
    int d = threadIdx.x;       // 0..63
    double inv = pow(50000.0, -2.0 * (double)d / 128.0);
    double ang = (double)s * inv;
    float c  = (float)cos(ang);
    float sn = (float)sin(ang);

    float* row = qkv + (size_t)s * QKV_N;
#pragma unroll 1
    for (int h = 0; h < NH + NG; h++) {
        float* base = (h < NH) ? (row + h * HD)
                               : (row + MODEL_DIM + (h - NH) * HD);
        float x1 = base[d];
        float x2 = base[d + 64];
        base[d]      = x1 * c - x2 * sn;
        base[d + 64] = x2 * c + x1 * sn;
    }
}

// ---------------------------------------------------------------------------
// Causal GQA flash attention.
// Grid: (S/64, NH). Block: 256 threads (tx 0..15, ty 0..15).
// Per-thread: 4 query rows (ty*4..+4) x full online-softmax state; score tile
// 4x4 (cols tx*4..+4); output accumulator 4 rows x 8 d-cols (tx*8..+8).
// ---------------------------------------------------------------------------
#define QS_STRIDE 132
#define PS_STRIDE 68
#define ATTN_SMEM ((3 * 64 * QS_STRIDE + 64 * PS_STRIDE) * 4)

__global__ __launch_bounds__(256) void attn_kernel(
    const float* __restrict__ qkv, float* __restrict__ out)
{
    extern __shared__ float sm[];
    float* Qs = sm;                        // [64][132]
    float* Ks = Qs + 64 * QS_STRIDE;       // [64][132]
    float* Vs = Ks + 64 * QS_STRIDE;       // [64][132]
    float* Ps = Vs + 64 * QS_STRIDE;       // [64][68]

    int tid = threadIdx.x;
    int tx = tid % 16;
    int ty = tid / 16;
    int mb = blockIdx.x;
    int h  = blockIdx.y;
    int kvh = h >> 2;                      // G = NH/NG = 4
    int m0 = mb * 64;
    const float scale = 0.08838834764831843f;  // 1/sqrt(128)

    // Load + pre-scale Q tile
    for (int idx = tid; idx < 64 * 32; idx += 256) {
        int r  = idx / 32;
        int c4 = (idx % 32) * 4;
        float4 v = *(const float4*)&qkv[(size_t)(m0 + r) * QKV_N + h * HD + c4];
        v.x *= scale; v.y *= scale; v.z *= scale; v.w *= scale;
        *(float4*)&Qs[r * QS_STRIDE + c4] = v;
    }

    float m_i[4], l_i[4], acc[4][8];
#pragma unroll
    for (int i = 0; i < 4; i++) {
        m_i[i] = -INFINITY;
        l_i[i] = 0.f;
#pragma unroll
        for (int j = 0; j < 8; j++) acc[i][j] = 0.f;
    }

    int nkb = mb + 1;   // causal: kv blocks 0..mb
    for (int kb = 0; kb < nkb; kb++) {
        int k0 = kb * 64;
        // Load K, V tiles
        for (int idx = tid; idx < 64 * 32; idx += 256) {
            int r  = idx / 32;
            int c4 = (idx % 32) * 4;
            size_t base = (size_t)(k0 + r) * QKV_N + MODEL_DIM + kvh * HD + c4;
            *(float4*)&Ks[r * QS_STRIDE + c4] = *(const float4*)&qkv[base];
            *(float4*)&Vs[r * QS_STRIDE + c4] = *(const float4*)&qkv[base + KV_DIM];
        }
        __syncthreads();

        // S = Q K^T  (4x4 micro-tile)
        float s[4][4];
#pragma unroll
        for (int i = 0; i < 4; i++)
#pragma unroll
            for (int j = 0; j < 4; j++) s[i][j] = 0.f;

        for (int d = 0; d < HD; d += 4) {
            float4 qv[4], kv[4];
#pragma unroll
            for (int i = 0; i < 4; i++)
                qv[i] = *(float4*)&Qs[(ty * 4 + i) * QS_STRIDE + d];
#pragma unroll
            for (int j = 0; j < 4; j++)
                kv[j] = *(float4*)&Ks[(tx * 4 + j) * QS_STRIDE + d];
#pragma unroll
            for (int i = 0; i < 4; i++)
#pragma unroll
                for (int j = 0; j < 4; j++) {
                    s[i][j] = fmaf(qv[i].x, kv[j].x, s[i][j]);
                    s[i][j] = fmaf(qv[i].y, kv[j].y, s[i][j]);
                    s[i][j] = fmaf(qv[i].z, kv[j].z, s[i][j]);
                    s[i][j] = fmaf(qv[i].w, kv[j].w, s[i][j]);
                }
        }

        // Causal mask (only diagonal block is partial; blocks are aligned)
        if (kb == mb) {
#pragma unroll
            for (int i = 0; i < 4; i++)
#pragma unroll
                for (int j = 0; j < 4; j++)
                    if (tx * 4 + j > ty * 4 + i) s[i][j] = -INFINITY;
        }

        // Online softmax update. Rows are owned per-ty; reduce across tx
        // group = 16 lanes (lane%16 == tx), so shfl_xor 1,2,4,8 suffices.
#pragma unroll
        for (int i = 0; i < 4; i++) {
            float mx = fmaxf(fmaxf(s[i][0], s[i][1]), fmaxf(s[i][2], s[i][3]));
#pragma unroll
            for (int off = 1; off < 16; off <<= 1)
                mx = fmaxf(mx, __shfl_xor_sync(0xffffffffu, mx, off));

            float mnew  = fmaxf(m_i[i], mx);
            float alpha = expf(m_i[i] - mnew);   // 0 on first block (m_i=-inf)

            float rsum = 0.f;
#pragma unroll
            for (int j = 0; j < 4; j++) {
                float p = expf(s[i][j] - mnew);
                rsum += p;
                Ps[(ty * 4 + i) * PS_STRIDE + tx * 4 + j] = p;
            }
#pragma unroll
            for (int off = 1; off < 16; off <<= 1)
                rsum += __shfl_xor_sync(0xffffffffu, rsum, off);

            l_i[i] = l_i[i] * alpha + rsum;
            m_i[i] = mnew;
#pragma unroll
            for (int j = 0; j < 8; j++) acc[i][j] *= alpha;
        }
        __syncthreads();

        // O += P @ V : rows ty*4..+4, d-cols tx*8..+8
#pragma unroll 4
        for (int j = 0; j < 64; j++) {
            float pr[4];
#pragma unroll
            for (int i = 0; i < 4; i++)
                pr[i] = Ps[(ty * 4 + i) * PS_STRIDE + j];
            float4 v0 = *(float4*)&Vs[j * QS_STRIDE + tx * 8];
            float4 v1 = *(float4*)&Vs[j * QS_STRIDE + tx * 8 + 4];
#pragma unroll
            for (int i = 0; i < 4; i++) {
                acc[i][0] = fmaf(pr[i], v0.x, acc[i][0]);
                acc[i][1] = fmaf(pr[i], v0.y, acc[i][1]);
                acc[i][2] = fmaf(pr[i], v0.z, acc[i][2]);
                acc[i][3] = fmaf(pr[i], v0.w, acc[i][3]);
                acc[i][4] = fmaf(pr[i], v1.x, acc[i][4]);
                acc[i][5] = fmaf(pr[i], v1.y, acc[i][5]);
                acc[i][6] = fmaf(pr[i], v1.z, acc[i][6]);
                acc[i][7] = fmaf(pr[i], v1.w, acc[i][7]);
            }
        }
        __syncthreads();   // protect Ks/Vs/Ps before next iteration
    }

    // Normalize and write out: out[s, h*128 + d]
#pragma unroll
    for (int i = 0; i < 4; i++) {
        float inv_l = 1.f / l_i[i];
        int r = m0 + ty * 4 + i;
        float4 o0, o1;
        o0.x = acc[i][0] * inv_l; o0.y = acc[i][1] * inv_l;
        o0.z = acc[i][2] * inv_l; o0.w = acc[i][3] * inv_l;
        o1.x = acc[i][4] * inv_l; o1.y = acc[i][5] * inv_l;
        o1.z = acc[i][6] * inv_l; o1.w = acc[i][7] * inv_l;
        size_t base = (size_t)r * MODEL_DIM + h * HD + tx * 8;
        *(float4*)&out[base]     = o0;
        *(float4*)&out[base + 4] = o1;
    }
}

// ---------------------------------------------------------------------------
extern "C" void kernel_launch(void* const* d_in, const int* in_sizes, int n_in,
                              void* d_out, int out_size)
{
    const float* x    = (const float*)d_in[0];
    const float* Wqkv = (const float*)d_in[1];
    const float* bqkv = (const float*)d_in[2];
    const float* Wo   = (const float*)d_in[3];
    const float* bo   = (const float*)d_in[4];
    float* out = (float*)d_out;

    float *qkv_ptr = nullptr, *attn_ptr = nullptr;
    cudaGetSymbolAddress((void**)&qkv_ptr, g_qkv);
    cudaGetSymbolAddress((void**)&attn_ptr, g_attn);

    // 1) QKV projection: [2048,4096] @ [4096,6144] + bias
    {
        dim3 grid(QKV_N / 128, S_LEN / 128);
        sgemm_bias_kernel<<<grid, 256>>>(x, Wqkv, bqkv, qkv_ptr,
                                         S_LEN, QKV_N, MODEL_DIM);
    }

    // 2) RoPE on Q and K (in place)
    rope_kernel<<<S_LEN, 64>>>(qkv_ptr);

    // 3) Causal GQA attention
    {
        cudaFuncSetAttribute(attn_kernel,
                             cudaFuncAttributeMaxDynamicSharedMemorySize,
                             ATTN_SMEM);
        dim3 grid(S_LEN / 64, NH);
        attn_kernel<<<grid, 256, ATTN_SMEM>>>(qkv_ptr, attn_ptr);
    }

    // 4) Output projection: [2048,4096] @ [4096,4096] + bias
    {
        dim3 grid(MODEL_DIM / 128, S_LEN / 128);
        sgemm_bias_kernel<<<grid, 256>>>(attn_ptr, Wo, bo, out,
                                         S_LEN, MODEL_DIM, MODEL_DIM);
    }
}

// round 2
// speedup vs baseline: 1.8574x; 1.8574x over previous
#include <cuda_runtime.h>
#include <math.h>
#include <stdint.h>

#define MODEL_DIM 4096
#define NH 32
#define NG 8
#define HD 128
#define KV_DIM 1024                       // NG*HD
#define QKV_N (MODEL_DIM + 2 * KV_DIM)    // 6144
#define S_LEN 2048

// Scratch (allocation-free rule: __device__ globals)
__device__ float g_qkv[S_LEN * QKV_N];      // [2048, 6144]
__device__ float g_attn[S_LEN * MODEL_DIM]; // [2048, 4096]

// ---------------------------------------------------------------------------
// TF32 tensor-core GEMM: C[M,N] = A[M,K] @ B[K,N] + bias[N]  (row-major fp32)
// 128x128x32 tiles, 256 threads (8 warps, 2x4), warp tile 64x32,
// mma.sync.m16n8k8.tf32, cp.async double buffering.
// ---------------------------------------------------------------------------
#define BM 128
#define BN 128
#define BK 32
#define A_STRIDE 36    // BK + 4  -> conflict-free A fragment loads
#define B_STRIDE 136   // BN + 8  -> conflict-free B fragment loads
#define A_TILE (BM * A_STRIDE)
#define B_TILE (BK * B_STRIDE)
#define GEMM_SMEM ((2 * A_TILE + 2 * B_TILE) * 4)

__device__ __forceinline__ uint32_t f2tf32(float x) {
    uint32_t t;
    asm("cvt.rna.tf32.f32 %0, %1;" : "=r"(t) : "f"(x));
    return t;
}

__device__ __forceinline__ void mma_tf32(float c[4],
                                         uint32_t a0, uint32_t a1, uint32_t a2, uint32_t a3,
                                         uint32_t b0, uint32_t b1) {
    asm volatile(
        "mma.sync.aligned.m16n8k8.row.col.f32.tf32.tf32.f32 "
        "{%0,%1,%2,%3}, {%4,%5,%6,%7}, {%8,%9}, {%0,%1,%2,%3};\n"
        : "+f"(c[0]), "+f"(c[1]), "+f"(c[2]), "+f"(c[3])
        : "r"(a0), "r"(a1), "r"(a2), "r"(a3), "r"(b0), "r"(b1));
}

__device__ __forceinline__ void cp_async16(uint32_t smem_addr, const void* gptr) {
    asm volatile("cp.async.cg.shared.global [%0], [%1], 16;\n"
                 :: "r"(smem_addr), "l"(gptr));
}

__global__ __launch_bounds__(256, 2) void gemm_tf32_kernel(
    const float* __restrict__ A, const float* __restrict__ B,
    const float* __restrict__ bias, float* __restrict__ C,
    int M, int N, int K)
{
    extern __shared__ float sm[];
    float* As = sm;                 // [2][BM][A_STRIDE]
    float* Bs = sm + 2 * A_TILE;    // [2][BK][B_STRIDE]

    const int tid  = threadIdx.x;
    const int warp = tid >> 5;
    const int lane = tid & 31;
    const int wm = warp & 1;        // 2 warps along M (64 rows each)
    const int wn = warp >> 1;       // 4 warps along N (32 cols each)
    const int bm = blockIdx.y * BM;
    const int bn = blockIdx.x * BN;

    const uint32_t as_base = (uint32_t)__cvta_generic_to_shared(As);
    const uint32_t bs_base = (uint32_t)__cvta_generic_to_shared(Bs);

    float acc[4][4][4];
#pragma unroll
    for (int mt = 0; mt < 4; mt++)
#pragma unroll
        for (int nt = 0; nt < 4; nt++)
#pragma unroll
            for (int e = 0; e < 4; e++) acc[mt][nt][e] = 0.f;

    // precomputed copy coordinates (4 chunks each for A and B per thread)
    const int ar = tid >> 3;            // A: rows 0..127 come from idx>>3
    const int ak = (tid & 7) * 4;       // float offset
    const int br = tid >> 5;            // B rows from idx>>5
    const int bc = (tid & 31) * 4;

    auto load_stage = [&](int stage, int k0) {
#pragma unroll
        for (int t = 0; t < 4; t++) {
            int r = ar + t * 32;        // (tid + t*256)>>3
            cp_async16(as_base + (uint32_t)((stage * A_TILE + r * A_STRIDE + ak) * 4),
                       A + (size_t)(bm + r) * K + k0 + ak);
        }
#pragma unroll
        for (int t = 0; t < 4; t++) {
            int r = br + t * 8;         // (tid + t*256)>>5
            cp_async16(bs_base + (uint32_t)((stage * B_TILE + r * B_STRIDE + bc) * 4),
                       B + (size_t)(k0 + r) * N + bn + bc);
        }
    };

    load_stage(0, 0);
    asm volatile("cp.async.commit_group;\n");

    const int nstages = K / BK;
    for (int ks = 0; ks < nstages; ks++) {
        if (ks + 1 < nstages) {
            load_stage((ks + 1) & 1, (ks + 1) * BK);
            asm volatile("cp.async.commit_group;\n");
            asm volatile("cp.async.wait_group 1;\n");
        } else {
            asm volatile("cp.async.wait_group 0;\n");
        }
        __syncthreads();

        const float* as = As + (ks & 1) * A_TILE;
        const float* bs = Bs + (ks & 1) * B_TILE;

#pragma unroll
        for (int kk = 0; kk < BK; kk += 8) {
            uint32_t af[4][4];
#pragma unroll
            for (int mt = 0; mt < 4; mt++) {
                int r0 = wm * 64 + mt * 16 + (lane >> 2);
                int c0 = kk + (lane & 3);
                af[mt][0] = f2tf32(as[r0 * A_STRIDE + c0]);
                af[mt][1] = f2tf32(as[(r0 + 8) * A_STRIDE + c0]);
                af[mt][2] = f2tf32(as[r0 * A_STRIDE + c0 + 4]);
                af[mt][3] = f2tf32(as[(r0 + 8) * A_STRIDE + c0 + 4]);
            }
            uint32_t bf[4][2];
#pragma unroll
            for (int nt = 0; nt < 4; nt++) {
                int kr = kk + (lane & 3);
                int nc = wn * 32 + nt * 8 + (lane >> 2);
                bf[nt][0] = f2tf32(bs[kr * B_STRIDE + nc]);
                bf[nt][1] = f2tf32(bs[(kr + 4) * B_STRIDE + nc]);
            }
#pragma unroll
            for (int mt = 0; mt < 4; mt++)
#pragma unroll
                for (int nt = 0; nt < 4; nt++)
                    mma_tf32(acc[mt][nt],
                             af[mt][0], af[mt][1], af[mt][2], af[mt][3],
                             bf[nt][0], bf[nt][1]);
        }
        __syncthreads();
    }

    // Epilogue: add bias, store (float2 per c-pair)
#pragma unroll
    for (int mt = 0; mt < 4; mt++) {
        int r0 = bm + wm * 64 + mt * 16 + (lane >> 2);
#pragma unroll
        for (int nt = 0; nt < 4; nt++) {
            int c = bn + wn * 32 + nt * 8 + (lane & 3) * 2;
            float2 bv = *(const float2*)&bias[c];
            float2 o0, o1;
            o0.x = acc[mt][nt][0] + bv.x;
            o0.y = acc[mt][nt][1] + bv.y;
            o1.x = acc[mt][nt][2] + bv.x;
            o1.y = acc[mt][nt][3] + bv.y;
            *(float2*)&C[(size_t)r0 * N + c]       = o0;
            *(float2*)&C[(size_t)(r0 + 8) * N + c] = o1;
        }
    }
}

// ---------------------------------------------------------------------------
// RoPE in-place on Q (32 heads) and K (8 heads).
// ---------------------------------------------------------------------------
__global__ __launch_bounds__(64) void rope_kernel(float* __restrict__ qkv)
{
    int s = blockIdx.x;
    int d = threadIdx.x;
    double inv = pow(50000.0, -2.0 * (double)d / 128.0);
    double ang = (double)s * inv;
    float c  = (float)cos(ang);
    float sn = (float)sin(ang);

    float* row = qkv + (size_t)s * QKV_N;
#pragma unroll 1
    for (int h = 0; h < NH + NG; h++) {
        float* base = (h < NH) ? (row + h * HD)
                               : (row + MODEL_DIM + (h - NH) * HD);
        float x1 = base[d];
        float x2 = base[d + 64];
        base[d]      = x1 * c - x2 * sn;
        base[d + 64] = x2 * c + x1 * sn;
    }
}

// ---------------------------------------------------------------------------
// Causal GQA flash attention (fp32 SIMT). Grid: (S/64, NH). Block: 256.
// ---------------------------------------------------------------------------
#define QS_STRIDE 132
#define PS_STRIDE 68
#define ATTN_SMEM ((3 * 64 * QS_STRIDE + 64 * PS_STRIDE) * 4)

__global__ __launch_bounds__(256) void attn_kernel(
    const float* __restrict__ qkv, float* __restrict__ out)
{
    extern __shared__ float sm[];
    float* Qs = sm;
    float* Ks = Qs + 64 * QS_STRIDE;
    float* Vs = Ks + 64 * QS_STRIDE;
    float* Ps = Vs + 64 * QS_STRIDE;

    int tid = threadIdx.x;
    int tx = tid % 16;
    int ty = tid / 16;
    int mb = blockIdx.x;
    int h  = blockIdx.y;
    int kvh = h >> 2;
    int m0 = mb * 64;
    const float scale = 0.08838834764831843f;

    for (int idx = tid; idx < 64 * 32; idx += 256) {
        int r  = idx / 32;
        int c4 = (idx % 32) * 4;
        float4 v = *(const float4*)&qkv[(size_t)(m0 + r) * QKV_N + h * HD + c4];
        v.x *= scale; v.y *= scale; v.z *= scale; v.w *= scale;
        *(float4*)&Qs[r * QS_STRIDE + c4] = v;
    }

    float m_i[4], l_i[4], acc[4][8];
#pragma unroll
    for (int i = 0; i < 4; i++) {
        m_i[i] = -INFINITY;
        l_i[i] = 0.f;
#pragma unroll
        for (int j = 0; j < 8; j++) acc[i][j] = 0.f;
    }

    int nkb = mb + 1;
    for (int kb = 0; kb < nkb; kb++) {
        int k0 = kb * 64;
        for (int idx = tid; idx < 64 * 32; idx += 256) {
            int r  = idx / 32;
            int c4 = (idx % 32) * 4;
            size_t base = (size_t)(k0 + r) * QKV_N + MODEL_DIM + kvh * HD + c4;
            *(float4*)&Ks[r * QS_STRIDE + c4] = *(const float4*)&qkv[base];
            *(float4*)&Vs[r * QS_STRIDE + c4] = *(const float4*)&qkv[base + KV_DIM];
        }
        __syncthreads();

        float s[4][4];
#pragma unroll
        for (int i = 0; i < 4; i++)
#pragma unroll
            for (int j = 0; j < 4; j++) s[i][j] = 0.f;

        for (int d = 0; d < HD; d += 4) {
            float4 qv[4], kv[4];
#pragma unroll
            for (int i = 0; i < 4; i++)
                qv[i] = *(float4*)&Qs[(ty * 4 + i) * QS_STRIDE + d];
#pragma unroll
            for (int j = 0; j < 4; j++)
                kv[j] = *(float4*)&Ks[(tx * 4 + j) * QS_STRIDE + d];
#pragma unroll
            for (int i = 0; i < 4; i++)
#pragma unroll
                for (int j = 0; j < 4; j++) {
                    s[i][j] = fmaf(qv[i].x, kv[j].x, s[i][j]);
                    s[i][j] = fmaf(qv[i].y, kv[j].y, s[i][j]);
                    s[i][j] = fmaf(qv[i].z, kv[j].z, s[i][j]);
                    s[i][j] = fmaf(qv[i].w, kv[j].w, s[i][j]);
                }
        }

        if (kb == mb) {
#pragma unroll
            for (int i = 0; i < 4; i++)
#pragma unroll
                for (int j = 0; j < 4; j++)
                    if (tx * 4 + j > ty * 4 + i) s[i][j] = -INFINITY;
        }

#pragma unroll
        for (int i = 0; i < 4; i++) {
            float mx = fmaxf(fmaxf(s[i][0], s[i][1]), fmaxf(s[i][2], s[i][3]));
#pragma unroll
            for (int off = 1; off < 16; off <<= 1)
                mx = fmaxf(mx, __shfl_xor_sync(0xffffffffu, mx, off));

            float mnew  = fmaxf(m_i[i], mx);
            float alpha = expf(m_i[i] - mnew);

            float rsum = 0.f;
#pragma unroll
            for (int j = 0; j < 4; j++) {
                float p = expf(s[i][j] - mnew);
                rsum += p;
                Ps[(ty * 4 + i) * PS_STRIDE + tx * 4 + j] = p;
            }
#pragma unroll
            for (int off = 1; off < 16; off <<= 1)
                rsum += __shfl_xor_sync(0xffffffffu, rsum, off);

            l_i[i] = l_i[i] * alpha + rsum;
            m_i[i] = mnew;
#pragma unroll
            for (int j = 0; j < 8; j++) acc[i][j] *= alpha;
        }
        __syncthreads();

#pragma unroll 4
        for (int j = 0; j < 64; j++) {
            float pr[4];
#pragma unroll
            for (int i = 0; i < 4; i++)
                pr[i] = Ps[(ty * 4 + i) * PS_STRIDE + j];
            float4 v0 = *(float4*)&Vs[j * QS_STRIDE + tx * 8];
            float4 v1 = *(float4*)&Vs[j * QS_STRIDE + tx * 8 + 4];
#pragma unroll
            for (int i = 0; i < 4; i++) {
                acc[i][0] = fmaf(pr[i], v0.x, acc[i][0]);
                acc[i][1] = fmaf(pr[i], v0.y, acc[i][1]);
                acc[i][2] = fmaf(pr[i], v0.z, acc[i][2]);
                acc[i][3] = fmaf(pr[i], v0.w, acc[i][3]);
                acc[i][4] = fmaf(pr[i], v1.x, acc[i][4]);
                acc[i][5] = fmaf(pr[i], v1.y, acc[i][5]);
                acc[i][6] = fmaf(pr[i], v1.z, acc[i][6]);
                acc[i][7] = fmaf(pr[i], v1.w, acc[i][7]);
            }
        }
        __syncthreads();
    }

#pragma unroll
    for (int i = 0; i < 4; i++) {
        float inv_l = 1.f / l_i[i];
        int r = m0 + ty * 4 + i;
        float4 o0, o1;
        o0.x = acc[i][0] * inv_l; o0.y = acc[i][1] * inv_l;
        o0.z = acc[i][2] * inv_l; o0.w = acc[i][3] * inv_l;
        o1.x = acc[i][4] * inv_l; o1.y = acc[i][5] * inv_l;
        o1.z = acc[i][6] * inv_l; o1.w = acc[i][7] * inv_l;
        size_t base = (size_t)r * MODEL_DIM + h * HD + tx * 8;
        *(float4*)&out[base]     = o0;
        *(float4*)&out[base + 4] = o1;
    }
}

// ---------------------------------------------------------------------------
extern "C" void kernel_launch(void* const* d_in, const int* in_sizes, int n_in,
                              void* d_out, int out_size)
{
    const float* x    = (const float*)d_in[0];
    const float* Wqkv = (const float*)d_in[1];
    const float* bqkv = (const float*)d_in[2];
    const float* Wo   = (const float*)d_in[3];
    const float* bo   = (const float*)d_in[4];
    float* out = (float*)d_out;

    float *qkv_ptr = nullptr, *attn_ptr = nullptr;
    cudaGetSymbolAddress((void**)&qkv_ptr, g_qkv);
    cudaGetSymbolAddress((void**)&attn_ptr, g_attn);

    static bool attr_set = false;
    if (!attr_set) {
        cudaFuncSetAttribute(gemm_tf32_kernel,
                             cudaFuncAttributeMaxDynamicSharedMemorySize, GEMM_SMEM);
        cudaFuncSetAttribute(attn_kernel,
                             cudaFuncAttributeMaxDynamicSharedMemorySize, ATTN_SMEM);
        attr_set = true;
    }

    // 1) QKV projection: [2048,4096] @ [4096,6144] + bias (TF32 tensor cores)
    {
        dim3 grid(QKV_N / BN, S_LEN / BM);
        gemm_tf32_kernel<<<grid, 256, GEMM_SMEM>>>(x, Wqkv, bqkv, qkv_ptr,
                                                   S_LEN, QKV_N, MODEL_DIM);
    }

    // 2) RoPE on Q and K (in place)
    rope_kernel<<<S_LEN, 64>>>(qkv_ptr);

    // 3) Causal GQA attention (fp32)
    {
        dim3 grid(S_LEN / 64, NH);
        attn_kernel<<<grid, 256, ATTN_SMEM>>>(qkv_ptr, attn_ptr);
    }

    // 4) Output projection: [2048,4096] @ [4096,4096] + bias (TF32 tensor cores)
    {
        dim3 grid(MODEL_DIM / BN, S_LEN / BM);
        gemm_tf32_kernel<<<grid, 256, GEMM_SMEM>>>(attn_ptr, Wo, bo, out,
                                                   S_LEN, MODEL_DIM, MODEL_DIM);
    }
}

// round 3
// speedup vs baseline: 3.5972x; 1.9366x over previous
#include <cuda_runtime.h>
#include <cuda_bf16.h>
#include <math.h>
#include <stdint.h>

#define MODEL_DIM 4096
#define NH 32
#define NG 8
#define HD 128
#define KV_DIM 1024                       // NG*HD
#define QKV_N (MODEL_DIM + 2 * KV_DIM)    // 6144
#define S_LEN 2048

// Scratch (allocation-free rule: __device__ globals)
__device__ float g_qkv[S_LEN * QKV_N];      // [2048, 6144]
__device__ float g_attn[S_LEN * MODEL_DIM]; // [2048, 4096]

// ---------------------------------------------------------------------------
// TF32 tensor-core GEMM (unchanged from R2): C = A@B + bias
// ---------------------------------------------------------------------------
#define BM 128
#define BN 128
#define BK 32
#define A_STRIDE 36
#define B_STRIDE 136
#define A_TILE (BM * A_STRIDE)
#define B_TILE (BK * B_STRIDE)
#define GEMM_SMEM ((2 * A_TILE + 2 * B_TILE) * 4)

__device__ __forceinline__ uint32_t f2tf32(float x) {
    uint32_t t;
    asm("cvt.rna.tf32.f32 %0, %1;" : "=r"(t) : "f"(x));
    return t;
}

__device__ __forceinline__ void mma_tf32(float c[4],
                                         uint32_t a0, uint32_t a1, uint32_t a2, uint32_t a3,
                                         uint32_t b0, uint32_t b1) {
    asm volatile(
        "mma.sync.aligned.m16n8k8.row.col.f32.tf32.tf32.f32 "
        "{%0,%1,%2,%3}, {%4,%5,%6,%7}, {%8,%9}, {%0,%1,%2,%3};\n"
        : "+f"(c[0]), "+f"(c[1]), "+f"(c[2]), "+f"(c[3])
        : "r"(a0), "r"(a1), "r"(a2), "r"(a3), "r"(b0), "r"(b1));
}

__device__ __forceinline__ void cp_async16(uint32_t smem_addr, const void* gptr) {
    asm volatile("cp.async.cg.shared.global [%0], [%1], 16;\n"
                 :: "r"(smem_addr), "l"(gptr));
}

__global__ __launch_bounds__(256, 2) void gemm_tf32_kernel(
    const float* __restrict__ A, const float* __restrict__ B,
    const float* __restrict__ bias, float* __restrict__ C,
    int M, int N, int K)
{
    extern __shared__ float sm[];
    float* As = sm;
    float* Bs = sm + 2 * A_TILE;

    const int tid  = threadIdx.x;
    const int warp = tid >> 5;
    const int lane = tid & 31;
    const int wm = warp & 1;
    const int wn = warp >> 1;
    const int bm = blockIdx.y * BM;
    const int bn = blockIdx.x * BN;

    const uint32_t as_base = (uint32_t)__cvta_generic_to_shared(As);
    const uint32_t bs_base = (uint32_t)__cvta_generic_to_shared(Bs);

    float acc[4][4][4];
#pragma unroll
    for (int mt = 0; mt < 4; mt++)
#pragma unroll
        for (int nt = 0; nt < 4; nt++)
#pragma unroll
            for (int e = 0; e < 4; e++) acc[mt][nt][e] = 0.f;

    const int ar = tid >> 3;
    const int ak = (tid & 7) * 4;
    const int br = tid >> 5;
    const int bc = (tid & 31) * 4;

    auto load_stage = [&](int stage, int k0) {
#pragma unroll
        for (int t = 0; t < 4; t++) {
            int r = ar + t * 32;
            cp_async16(as_base + (uint32_t)((stage * A_TILE + r * A_STRIDE + ak) * 4),
                       A + (size_t)(bm + r) * K + k0 + ak);
        }
#pragma unroll
        for (int t = 0; t < 4; t++) {
            int r = br + t * 8;
            cp_async16(bs_base + (uint32_t)((stage * B_TILE + r * B_STRIDE + bc) * 4),
                       B + (size_t)(k0 + r) * N + bn + bc);
        }
    };

    load_stage(0, 0);
    asm volatile("cp.async.commit_group;\n");

    const int nstages = K / BK;
    for (int ks = 0; ks < nstages; ks++) {
        if (ks + 1 < nstages) {
            load_stage((ks + 1) & 1, (ks + 1) * BK);
            asm volatile("cp.async.commit_group;\n");
            asm volatile("cp.async.wait_group 1;\n");
        } else {
            asm volatile("cp.async.wait_group 0;\n");
        }
        __syncthreads();

        const float* as = As + (ks & 1) * A_TILE;
        const float* bs = Bs + (ks & 1) * B_TILE;

#pragma unroll
        for (int kk = 0; kk < BK; kk += 8) {
            uint32_t af[4][4];
#pragma unroll
            for (int mt = 0; mt < 4; mt++) {
                int r0 = wm * 64 + mt * 16 + (lane >> 2);
                int c0 = kk + (lane & 3);
                af[mt][0] = f2tf32(as[r0 * A_STRIDE + c0]);
                af[mt][1] = f2tf32(as[(r0 + 8) * A_STRIDE + c0]);
                af[mt][2] = f2tf32(as[r0 * A_STRIDE + c0 + 4]);
                af[mt][3] = f2tf32(as[(r0 + 8) * A_STRIDE + c0 + 4]);
            }
            uint32_t bf[4][2];
#pragma unroll
            for (int nt = 0; nt < 4; nt++) {
                int kr = kk + (lane & 3);
                int nc = wn * 32 + nt * 8 + (lane >> 2);
                bf[nt][0] = f2tf32(bs[kr * B_STRIDE + nc]);
                bf[nt][1] = f2tf32(bs[(kr + 4) * B_STRIDE + nc]);
            }
#pragma unroll
            for (int mt = 0; mt < 4; mt++)
#pragma unroll
                for (int nt = 0; nt < 4; nt++)
                    mma_tf32(acc[mt][nt],
                             af[mt][0], af[mt][1], af[mt][2], af[mt][3],
                             bf[nt][0], bf[nt][1]);
        }
        __syncthreads();
    }

#pragma unroll
    for (int mt = 0; mt < 4; mt++) {
        int r0 = bm + wm * 64 + mt * 16 + (lane >> 2);
#pragma unroll
        for (int nt = 0; nt < 4; nt++) {
            int c = bn + wn * 32 + nt * 8 + (lane & 3) * 2;
            float2 bv = *(const float2*)&bias[c];
            float2 o0, o1;
            o0.x = acc[mt][nt][0] + bv.x;
            o0.y = acc[mt][nt][1] + bv.y;
            o1.x = acc[mt][nt][2] + bv.x;
            o1.y = acc[mt][nt][3] + bv.y;
            *(float2*)&C[(size_t)r0 * N + c]       = o0;
            *(float2*)&C[(size_t)(r0 + 8) * N + c] = o1;
        }
    }
}

// ---------------------------------------------------------------------------
// RoPE in-place on Q and K.
// ---------------------------------------------------------------------------
__global__ __launch_bounds__(64) void rope_kernel(float* __restrict__ qkv)
{
    int s = blockIdx.x;
    int d = threadIdx.x;
    double inv = pow(50000.0, -2.0 * (double)d / 128.0);
    double ang = (double)s * inv;
    float c  = (float)cos(ang);
    float sn = (float)sin(ang);

    float* row = qkv + (size_t)s * QKV_N;
#pragma unroll 1
    for (int h = 0; h < NH + NG; h++) {
        float* base = (h < NH) ? (row + h * HD)
                               : (row + MODEL_DIM + (h - NH) * HD);
        float x1 = base[d];
        float x2 = base[d + 64];
        base[d]      = x1 * c - x2 * sn;
        base[d + 64] = x2 * c + x1 * sn;
    }
}

// ---------------------------------------------------------------------------
// bf16x3 tensor-core flash attention.
// Grid (16, 32): qtile (heaviest first) x head. Block 256 = 8 warps.
// Each warp owns 16 query rows -> warp-local softmax.
// Q/K/V/P split into bf16 hi+lo; products: hi*hi + hi*lo + lo*hi (fp32-accurate).
// ---------------------------------------------------------------------------
#define AQ_STRIDE 136   // bf16 elems per row (128 + 8 pad) -> conflict-free ldmatrix
#define AP_STRIDE 72    // P tile row stride (64 + 8)

#define OFF_QHI 0
#define OFF_QLO (OFF_QHI + 128 * AQ_STRIDE)
#define OFF_KHI (OFF_QLO + 128 * AQ_STRIDE)
#define OFF_KLO (OFF_KHI + 64 * AQ_STRIDE)
#define OFF_VHI (OFF_KLO + 64 * AQ_STRIDE)
#define OFF_VLO (OFF_VHI + 64 * AQ_STRIDE)
#define OFF_PHI (OFF_VLO + 64 * AQ_STRIDE)
#define OFF_PLO (OFF_PHI + 128 * AP_STRIDE)
#define ATTN_SMEM_BYTES ((OFF_PLO + 128 * AP_STRIDE) * 2)   // 176128 B

#define LDSM4(R0,R1,R2,R3,ADDR) \
    asm volatile("ldmatrix.sync.aligned.m8n8.x4.shared.b16 {%0,%1,%2,%3}, [%4];" \
                 : "=r"(R0),"=r"(R1),"=r"(R2),"=r"(R3) : "r"(ADDR))
#define LDSM4T(R0,R1,R2,R3,ADDR) \
    asm volatile("ldmatrix.sync.aligned.m8n8.x4.trans.shared.b16 {%0,%1,%2,%3}, [%4];" \
                 : "=r"(R0),"=r"(R1),"=r"(R2),"=r"(R3) : "r"(ADDR))

__device__ __forceinline__ void mma_bf16(float c[4],
                                         uint32_t a0, uint32_t a1, uint32_t a2, uint32_t a3,
                                         uint32_t b0, uint32_t b1) {
    asm volatile(
        "mma.sync.aligned.m16n8k16.row.col.f32.bf16.bf16.f32 "
        "{%0,%1,%2,%3}, {%4,%5,%6,%7}, {%8,%9}, {%0,%1,%2,%3};\n"
        : "+f"(c[0]), "+f"(c[1]), "+f"(c[2]), "+f"(c[3])
        : "r"(a0), "r"(a1), "r"(a2), "r"(a3), "r"(b0), "r"(b1));
}

// split a float into bf16 hi + bf16 lo (residual)
__device__ __forceinline__ void split_bf16(float x, __nv_bfloat16& hi, __nv_bfloat16& lo) {
    hi = __float2bfloat16(x);
    lo = __float2bfloat16(x - __bfloat162float(hi));
}

__global__ __launch_bounds__(256) void attn_mma_kernel(
    const float* __restrict__ qkv, float* __restrict__ out)
{
    extern __shared__ __nv_bfloat16 sb[];
    __nv_bfloat16* Qhi = sb + OFF_QHI;
    __nv_bfloat16* Qlo = sb + OFF_QLO;
    __nv_bfloat16* Khi = sb + OFF_KHI;
    __nv_bfloat16* Klo = sb + OFF_KLO;
    __nv_bfloat16* Vhi = sb + OFF_VHI;
    __nv_bfloat16* Vlo = sb + OFF_VLO;
    __nv_bfloat16* Phi = sb + OFF_PHI;
    __nv_bfloat16* Plo = sb + OFF_PLO;

    const int tid  = threadIdx.x;
    const int warp = tid >> 5;
    const int lane = tid & 31;
    const int mb = (gridDim.x - 1) - blockIdx.x;   // heavy tiles first
    const int h  = blockIdx.y;
    const int kvh = h >> 2;
    const int m0 = mb * 128;
    const float scale = 0.08838834764831843f;      // 1/sqrt(128)

    // ---- load + split Q (scale folded in) ----
#pragma unroll
    for (int t = 0; t < 16; t++) {
        int idx = tid + t * 256;
        int r  = idx >> 5;
        int c  = (idx & 31) * 4;
        float4 v = *(const float4*)&qkv[(size_t)(m0 + r) * QKV_N + h * HD + c];
        v.x *= scale; v.y *= scale; v.z *= scale; v.w *= scale;
        __nv_bfloat16 h0,h1,h2,h3,l0,l1,l2,l3;
        split_bf16(v.x,h0,l0); split_bf16(v.y,h1,l1);
        split_bf16(v.z,h2,l2); split_bf16(v.w,h3,l3);
        int o = r * AQ_STRIDE + c;
        *(__nv_bfloat162*)&Qhi[o]   = __nv_bfloat162{h0,h1};
        *(__nv_bfloat162*)&Qhi[o+2] = __nv_bfloat162{h2,h3};
        *(__nv_bfloat162*)&Qlo[o]   = __nv_bfloat162{l0,l1};
        *(__nv_bfloat162*)&Qlo[o+2] = __nv_bfloat162{l2,l3};
    }

    float mrow[2] = {-1e30f, -1e30f};
    float lrow[2] = {0.f, 0.f};
    float oacc[16][4];
#pragma unroll
    for (int nt = 0; nt < 16; nt++)
#pragma unroll
        for (int e = 0; e < 4; e++) oacc[nt][e] = 0.f;

    const int row0g = m0 + warp * 16 + (lane >> 2);
    const int row1g = row0g + 8;

    const int nkb = 2 * mb + 2;
    for (int kb = 0; kb < nkb; kb++) {
        const int k0 = kb * 64;
        __syncthreads();   // prev iteration's K/V reads done (also orders Q on iter 0)

        // ---- load + split K, V ----
#pragma unroll
        for (int t = 0; t < 8; t++) {
            int idx = tid + t * 256;
            int r  = idx >> 5;
            int c  = (idx & 31) * 4;
            size_t base = (size_t)(k0 + r) * QKV_N + MODEL_DIM + kvh * HD + c;
            float4 kv = *(const float4*)&qkv[base];
            float4 vv = *(const float4*)&qkv[base + KV_DIM];
            int o = r * AQ_STRIDE + c;
            __nv_bfloat16 h0,h1,h2,h3,l0,l1,l2,l3;
            split_bf16(kv.x,h0,l0); split_bf16(kv.y,h1,l1);
            split_bf16(kv.z,h2,l2); split_bf16(kv.w,h3,l3);
            *(__nv_bfloat162*)&Khi[o]   = __nv_bfloat162{h0,h1};
            *(__nv_bfloat162*)&Khi[o+2] = __nv_bfloat162{h2,h3};
            *(__nv_bfloat162*)&Klo[o]   = __nv_bfloat162{l0,l1};
            *(__nv_bfloat162*)&Klo[o+2] = __nv_bfloat162{l2,l3};
            split_bf16(vv.x,h0,l0); split_bf16(vv.y,h1,l1);
            split_bf16(vv.z,h2,l2); split_bf16(vv.w,h3,l3);
            *(__nv_bfloat162*)&Vhi[o]   = __nv_bfloat162{h0,h1};
            *(__nv_bfloat162*)&Vhi[o+2] = __nv_bfloat162{h2,h3};
            *(__nv_bfloat162*)&Vlo[o]   = __nv_bfloat162{l0,l1};
            *(__nv_bfloat162*)&Vlo[o+2] = __nv_bfloat162{l2,l3};
        }
        __syncthreads();

        // ---- S = Q K^T (bf16x3) ----
        float sacc[8][4];
#pragma unroll
        for (int nt = 0; nt < 8; nt++)
#pragma unroll
            for (int e = 0; e < 4; e++) sacc[nt][e] = 0.f;

        const int a_row = warp * 16 + (lane & 15);
        const int a_col8 = (lane >> 4) * 8;

#pragma unroll
        for (int ks = 0; ks < 8; ks++) {
            uint32_t ah[4], al[4];
            {
                uint32_t ad = (uint32_t)__cvta_generic_to_shared(
                    &Qhi[a_row * AQ_STRIDE + ks * 16 + a_col8]);
                LDSM4(ah[0], ah[1], ah[2], ah[3], ad);
                ad = (uint32_t)__cvta_generic_to_shared(
                    &Qlo[a_row * AQ_STRIDE + ks * 16 + a_col8]);
                LDSM4(al[0], al[1], al[2], al[3], ad);
            }
#pragma unroll
            for (int ng = 0; ng < 4; ng++) {
                uint32_t bh[4], bl[4];
                uint32_t bd = (uint32_t)__cvta_generic_to_shared(
                    &Khi[(ng * 16 + (lane & 15)) * AQ_STRIDE + ks * 16 + a_col8]);
                LDSM4(bh[0], bh[1], bh[2], bh[3], bd);
                bd = (uint32_t)__cvta_generic_to_shared(
                    &Klo[(ng * 16 + (lane & 15)) * AQ_STRIDE + ks * 16 + a_col8]);
                LDSM4(bl[0], bl[1], bl[2], bl[3], bd);
                int nt = ng * 2;
                mma_bf16(sacc[nt],   ah[0],ah[1],ah[2],ah[3], bh[0],bh[2]);
                mma_bf16(sacc[nt],   ah[0],ah[1],ah[2],ah[3], bl[0],bl[2]);
                mma_bf16(sacc[nt],   al[0],al[1],al[2],al[3], bh[0],bh[2]);
                mma_bf16(sacc[nt+1], ah[0],ah[1],ah[2],ah[3], bh[1],bh[3]);
                mma_bf16(sacc[nt+1], ah[0],ah[1],ah[2],ah[3], bl[1],bl[3]);
                mma_bf16(sacc[nt+1], al[0],al[1],al[2],al[3], bh[1],bh[3]);
            }
        }

        // ---- causal mask (only the two diagonal-adjacent tiles) ----
        if (k0 + 63 > m0) {
#pragma unroll
            for (int nt = 0; nt < 8; nt++) {
                int c = k0 + nt * 8 + 2 * (lane & 3);
                if (c     > row0g) sacc[nt][0] = -1e30f;
                if (c + 1 > row0g) sacc[nt][1] = -1e30f;
                if (c     > row1g) sacc[nt][2] = -1e30f;
                if (c + 1 > row1g) sacc[nt][3] = -1e30f;
            }
        }

        // ---- online softmax (warp-local: 4 lanes per row) ----
        float mx0 = -1e30f, mx1 = -1e30f;
#pragma unroll
        for (int nt = 0; nt < 8; nt++) {
            mx0 = fmaxf(mx0, fmaxf(sacc[nt][0], sacc[nt][1]));
            mx1 = fmaxf(mx1, fmaxf(sacc[nt][2], sacc[nt][3]));
        }
        mx0 = fmaxf(mx0, __shfl_xor_sync(0xffffffffu, mx0, 1));
        mx0 = fmaxf(mx0, __shfl_xor_sync(0xffffffffu, mx0, 2));
        mx1 = fmaxf(mx1, __shfl_xor_sync(0xffffffffu, mx1, 1));
        mx1 = fmaxf(mx1, __shfl_xor_sync(0xffffffffu, mx1, 2));

        float mn0 = fmaxf(mrow[0], mx0);
        float mn1 = fmaxf(mrow[1], mx1);
        float al0 = __expf(mrow[0] - mn0);
        float al1 = __expf(mrow[1] - mn1);

        const int prl0 = warp * 16 + (lane >> 2);
        float s0 = 0.f, s1 = 0.f;
#pragma unroll
        for (int nt = 0; nt < 8; nt++) {
            int col = nt * 8 + 2 * (lane & 3);
            float p00 = __expf(sacc[nt][0] - mn0);
            float p01 = __expf(sacc[nt][1] - mn0);
            float p10 = __expf(sacc[nt][2] - mn1);
            float p11 = __expf(sacc[nt][3] - mn1);
            s0 += p00 + p01;
            s1 += p10 + p11;
            __nv_bfloat16 h0,h1,l0,l1;
            split_bf16(p00,h0,l0); split_bf16(p01,h1,l1);
            *(__nv_bfloat162*)&Phi[prl0 * AP_STRIDE + col] = __nv_bfloat162{h0,h1};
            *(__nv_bfloat162*)&Plo[prl0 * AP_STRIDE + col] = __nv_bfloat162{l0,l1};
            split_bf16(p10,h0,l0); split_bf16(p11,h1,l1);
            *(__nv_bfloat162*)&Phi[(prl0+8) * AP_STRIDE + col] = __nv_bfloat162{h0,h1};
            *(__nv_bfloat162*)&Plo[(prl0+8) * AP_STRIDE + col] = __nv_bfloat162{l0,l1};
        }
        s0 += __shfl_xor_sync(0xffffffffu, s0, 1);
        s0 += __shfl_xor_sync(0xffffffffu, s0, 2);
        s1 += __shfl_xor_sync(0xffffffffu, s1, 1);
        s1 += __shfl_xor_sync(0xffffffffu, s1, 2);

        lrow[0] = lrow[0] * al0 + s0;
        lrow[1] = lrow[1] * al1 + s1;
        mrow[0] = mn0;
        mrow[1] = mn1;
#pragma unroll
        for (int nt = 0; nt < 16; nt++) {
            oacc[nt][0] *= al0; oacc[nt][1] *= al0;
            oacc[nt][2] *= al1; oacc[nt][3] *= al1;
        }
        __syncwarp();

        // ---- O += P V (bf16x3) ----
        const int v_row = (lane & 7) + 8 * ((lane >> 3) & 1);
        const int v_col8 = 8 * (lane >> 4);
#pragma unroll
        for (int ks = 0; ks < 4; ks++) {
            int kk = ks * 16;
            uint32_t ph[4], pl[4];
            uint32_t ad = (uint32_t)__cvta_generic_to_shared(
                &Phi[(warp * 16 + (lane & 15)) * AP_STRIDE + kk + a_col8]);
            LDSM4(ph[0], ph[1], ph[2], ph[3], ad);
            ad = (uint32_t)__cvta_generic_to_shared(
                &Plo[(warp * 16 + (lane & 15)) * AP_STRIDE + kk + a_col8]);
            LDSM4(pl[0], pl[1], pl[2], pl[3], ad);
#pragma unroll
            for (int dg = 0; dg < 8; dg++) {
                int db = dg * 16;
                uint32_t vh[4], vl[4];
                uint32_t vd = (uint32_t)__cvta_generic_to_shared(
                    &Vhi[(kk + v_row) * AQ_STRIDE + db + v_col8]);
                LDSM4T(vh[0], vh[1], vh[2], vh[3], vd);
                vd = (uint32_t)__cvta_generic_to_shared(
                    &Vlo[(kk + v_row) * AQ_STRIDE + db + v_col8]);
                LDSM4T(vl[0], vl[1], vl[2], vl[3], vd);
                int nt = dg * 2;
                mma_bf16(oacc[nt],   ph[0],ph[1],ph[2],ph[3], vh[0],vh[1]);
                mma_bf16(oacc[nt],   ph[0],ph[1],ph[2],ph[3], vl[0],vl[1]);
                mma_bf16(oacc[nt],   pl[0],pl[1],pl[2],pl[3], vh[0],vh[1]);
                mma_bf16(oacc[nt+1], ph[0],ph[1],ph[2],ph[3], vh[2],vh[3]);
                mma_bf16(oacc[nt+1], ph[0],ph[1],ph[2],ph[3], vl[2],vl[3]);
                mma_bf16(oacc[nt+1], pl[0],pl[1],pl[2],pl[3], vh[2],vh[3]);
            }
        }
        __syncwarp();   // P reads done before next tile overwrites
    }

    // ---- normalize + store ----
    float inv0 = 1.f / lrow[0];
    float inv1 = 1.f / lrow[1];
#pragma unroll
    for (int nt = 0; nt < 16; nt++) {
        int d = nt * 8 + 2 * (lane & 3);
        size_t b0 = (size_t)row0g * MODEL_DIM + h * HD + d;
        size_t b1 = (size_t)row1g * MODEL_DIM + h * HD + d;
        *(float2*)&out[b0] = float2{oacc[nt][0] * inv0, oacc[nt][1] * inv0};
        *(float2*)&out[b1] = float2{oacc[nt][2] * inv1, oacc[nt][3] * inv1};
    }
}

// ---------------------------------------------------------------------------
extern "C" void kernel_launch(void* const* d_in, const int* in_sizes, int n_in,
                              void* d_out, int out_size)
{
    const float* x    = (const float*)d_in[0];
    const float* Wqkv = (const float*)d_in[1];
    const float* bqkv = (const float*)d_in[2];
    const float* Wo   = (const float*)d_in[3];
    const float* bo   = (const float*)d_in[4];
    float* out = (float*)d_out;

    float *qkv_ptr = nullptr, *attn_ptr = nullptr;
    cudaGetSymbolAddress((void**)&qkv_ptr, g_qkv);
    cudaGetSymbolAddress((void**)&attn_ptr, g_attn);

    static bool attr_set = false;
    if (!attr_set) {
        cudaFuncSetAttribute(gemm_tf32_kernel,
                             cudaFuncAttributeMaxDynamicSharedMemorySize, GEMM_SMEM);
        cudaFuncSetAttribute(attn_mma_kernel,
                             cudaFuncAttributeMaxDynamicSharedMemorySize, ATTN_SMEM_BYTES);
        attr_set = true;
    }

    // 1) QKV projection (TF32 tensor cores)
    {
        dim3 grid(QKV_N / BN, S_LEN / BM);
        gemm_tf32_kernel<<<grid, 256, GEMM_SMEM>>>(x, Wqkv, bqkv, qkv_ptr,
                                                   S_LEN, QKV_N, MODEL_DIM);
    }

    // 2) RoPE on Q and K (in place)
    rope_kernel<<<S_LEN, 64>>>(qkv_ptr);

    // 3) Causal GQA attention (bf16x3 tensor cores)
    {
        dim3 grid(S_LEN / 128, NH);
        attn_mma_kernel<<<grid, 256, ATTN_SMEM_BYTES>>>(qkv_ptr, attn_ptr);
    }

    // 4) Output projection (TF32 tensor cores)
    {
        dim3 grid(MODEL_DIM / BN, S_LEN / BM);
        gemm_tf32_kernel<<<grid, 256, GEMM_SMEM>>>(attn_ptr, Wo, bo, out,
                                                   S_LEN, MODEL_DIM, MODEL_DIM);
    }
}

// round 5
// speedup vs baseline: 4.3928x; 1.2212x over previous
#include <cuda_runtime.h>
#include <cuda_bf16.h>
#include <math.h>
#include <stdint.h>

#define MODEL_DIM 4096
#define NH 32
#define NG 8
#define HD 128
#define KV_DIM 1024
#define QKV_N (MODEL_DIM + 2 * KV_DIM)    // 6144
#define S_LEN 2048

// ---------------- scratch (__device__ globals; no allocs allowed) ----------
__device__ float g_qkv[S_LEN * QKV_N];                        // fp32 qkv (RoPE in place)
__device__ float g_attn[S_LEN * MODEL_DIM];                   // fp32 attention out
__device__ float4 g_xpk[(S_LEN / 16) * (MODEL_DIM / 8) * 32];       // packed x
__device__ float4 g_apk[(S_LEN / 16) * (MODEL_DIM / 8) * 32];       // packed attn out
__device__ float4 g_wqkvpk[(QKV_N / 16) * (MODEL_DIM / 8) * 32];    // packed Wqkv^T
__device__ float4 g_wopk[(MODEL_DIM / 16) * (MODEL_DIM / 8) * 32];  // packed Wo^T

// ---------------- helpers --------------------------------------------------
__device__ __forceinline__ uint32_t f2tf32(float x) {
    uint32_t t;
    asm("cvt.rna.tf32.f32 %0, %1;" : "=r"(t) : "f"(x));
    return t;
}
__device__ __forceinline__ float tf32r(float x) { return __uint_as_float(f2tf32(x)); }

__device__ __forceinline__ void mma_tf32(float c[4],
                                         uint32_t a0, uint32_t a1, uint32_t a2, uint32_t a3,
                                         uint32_t b0, uint32_t b1) {
    asm volatile(
        "mma.sync.aligned.m16n8k8.row.col.f32.tf32.tf32.f32 "
        "{%0,%1,%2,%3}, {%4,%5,%6,%7}, {%8,%9}, {%0,%1,%2,%3};\n"
        : "+f"(c[0]), "+f"(c[1]), "+f"(c[2]), "+f"(c[3])
        : "r"(a0), "r"(a1), "r"(a2), "r"(a3), "r"(b0), "r"(b1));
}

__device__ __forceinline__ void cp_async16(uint32_t smem_addr, const void* gptr) {
    asm volatile("cp.async.cg.shared.global [%0], [%1], 16;\n"
                 :: "r"(smem_addr), "l"(gptr));
}

// ---------------------------------------------------------------------------
// Packing: A [M,K] row-major fp32 -> fragment-packed tf32.
// Subtile (mt, kt) = 16x8; lane holds {A[r][c], A[r+8][c], A[r][c+4], A[r+8][c+4]},
// r = mt*16 + (lane>>2), c = kt*8 + (lane&3). Stored [mt][kt][lane].
// ---------------------------------------------------------------------------
__global__ __launch_bounds__(256) void pack_a_kernel(
    const float* __restrict__ A, float4* __restrict__ pk, int M, int K)
{
    const int w = threadIdx.x >> 5, lane = threadIdx.x & 31;
    const int Kt = K >> 3;
    const int kt = blockIdx.x * 8 + w;
    const int mt = blockIdx.y;
    const int r = mt * 16 + (lane >> 2);
    const int c = kt * 8 + (lane & 3);
    float4 v;
    v.x = tf32r(A[(size_t)r * K + c]);
    v.y = tf32r(A[(size_t)(r + 8) * K + c]);
    v.z = tf32r(A[(size_t)r * K + c + 4]);
    v.w = tf32r(A[(size_t)(r + 8) * K + c + 4]);
    pk[((size_t)mt * Kt + kt) * 32 + lane] = v;
}

// B packing from W [K,N] row-major: fragment-packed W^T.
// Subtile-pair (np, kt): n16 x k8; lane holds {W[k][ne], W[k+4][ne], W[k][ne+8], W[k+4][ne+8]},
// k = kt*8 + (lane&3), ne = np*16 + (lane>>2). Stored [np][kt][lane].
__global__ __launch_bounds__(256) void pack_b_kernel(
    const float* __restrict__ W, float4* __restrict__ pk, int K, int N)
{
    const int w = threadIdx.x >> 5, lane = threadIdx.x & 31;
    const int Kt = K >> 3;
    const int kt = blockIdx.x * 8 + w;
    const int np = blockIdx.y;
    const int k = kt * 8 + (lane & 3);
    const int ne = np * 16 + (lane >> 2);
    float4 v;
    v.x = tf32r(W[(size_t)k * N + ne]);
    v.y = tf32r(W[(size_t)(k + 4) * N + ne]);
    v.z = tf32r(W[(size_t)k * N + ne + 8]);
    v.w = tf32r(W[(size_t)(k + 4) * N + ne + 8]);
    pk[((size_t)np * Kt + kt) * 32 + lane] = v;
}

// ---------------------------------------------------------------------------
// Fragment-packed TF32 GEMM: C[M,N] = A@B + bias. 128x128x32 tiles, 8 warps,
// warp tile 64x32. All fragment loads are single LDS.128; zero in-loop cvt.
// ---------------------------------------------------------------------------
#define GEMM_SMEM 65536   // 2 stages x (A 16KB + B 16KB)

__global__ __launch_bounds__(256, 2) void gemm_pk_kernel(
    const float4* __restrict__ Apk, const float4* __restrict__ Bpk,
    const float* __restrict__ bias, float* __restrict__ C,
    int M, int N, int K)
{
    extern __shared__ float4 sm4[];
    const int tid  = threadIdx.x;
    const int warp = tid >> 5;
    const int lane = tid & 31;
    const int wm = warp & 1;
    const int wn = warp >> 1;
    const int bm = blockIdx.y * 128;
    const int bn = blockIdx.x * 128;
    const int Kt = K >> 3;
    const uint32_t sbase = (uint32_t)__cvta_generic_to_shared(sm4);

    float acc[4][4][4];
#pragma unroll
    for (int mt = 0; mt < 4; mt++)
#pragma unroll
        for (int nt = 0; nt < 4; nt++)
#pragma unroll
            for (int e = 0; e < 4; e++) acc[mt][nt][e] = 0.f;

    auto load_stage = [&](int buf, int kt0) {
#pragma unroll
        for (int t = 0; t < 4; t++) {
            int c = tid + t * 256;
            int run = c >> 7, win = c & 127;
            const float4* g = Apk + ((size_t)((bm >> 4) + run) * Kt + kt0) * 32 + win;
            cp_async16(sbase + (uint32_t)(buf * 1024 + c) * 16, g);
        }
#pragma unroll
        for (int t = 0; t < 4; t++) {
            int c = tid + t * 256;
            int run = c >> 7, win = c & 127;
            const float4* g = Bpk + ((size_t)((bn >> 4) + run) * Kt + kt0) * 32 + win;
            cp_async16(sbase + (uint32_t)(2048 + buf * 1024 + c) * 16, g);
        }
        asm volatile("cp.async.commit_group;\n");
    };

    load_stage(0, 0);

    const int nstages = K >> 5;   // BK = 32 = 4 ktiles
    for (int ks = 0; ks < nstages; ks++) {
        if (ks + 1 < nstages) {
            load_stage((ks + 1) & 1, (ks + 1) * 4);
            asm volatile("cp.async.wait_group 1;\n");
        } else {
            asm volatile("cp.async.wait_group 0;\n");
        }
        __syncthreads();

        const float4* As_ = sm4 + (ks & 1) * 1024;
        const float4* Bs_ = sm4 + 2048 + (ks & 1) * 1024;

#pragma unroll
        for (int kk = 0; kk < 4; kk++) {
            float4 a[4];
#pragma unroll
            for (int mt = 0; mt < 4; mt++)
                a[mt] = As_[((wm * 4 + mt) * 4 + kk) * 32 + lane];
            float4 b[2];
#pragma unroll
            for (int p = 0; p < 2; p++)
                b[p] = Bs_[((wn * 2 + p) * 4 + kk) * 32 + lane];
#pragma unroll
            for (int mt = 0; mt < 4; mt++) {
                uint32_t a0 = __float_as_uint(a[mt].x);
                uint32_t a1 = __float_as_uint(a[mt].y);
                uint32_t a2 = __float_as_uint(a[mt].z);
                uint32_t a3 = __float_as_uint(a[mt].w);
#pragma unroll
                for (int p = 0; p < 2; p++) {
                    mma_tf32(acc[mt][2 * p],     a0, a1, a2, a3,
                             __float_as_uint(b[p].x), __float_as_uint(b[p].y));
                    mma_tf32(acc[mt][2 * p + 1], a0, a1, a2, a3,
                             __float_as_uint(b[p].z), __float_as_uint(b[p].w));
                }
            }
        }
        __syncthreads();
    }

    // Epilogue: add bias, store
#pragma unroll
    for (int mt = 0; mt < 4; mt++) {
        int r0 = bm + wm * 64 + mt * 16 + (lane >> 2);
#pragma unroll
        for (int p = 0; p < 2; p++) {
#pragma unroll
            for (int q = 0; q < 2; q++) {
                int nt = 2 * p + q;
                int c = bn + wn * 32 + p * 16 + q * 8 + (lane & 3) * 2;
                float2 bv = *(const float2*)&bias[c];
                float2 o0, o1;
                o0.x = acc[mt][nt][0] + bv.x;
                o0.y = acc[mt][nt][1] + bv.y;
                o1.x = acc[mt][nt][2] + bv.x;
                o1.y = acc[mt][nt][3] + bv.y;
                *(float2*)&C[(size_t)r0 * N + c]       = o0;
                *(float2*)&C[(size_t)(r0 + 8) * N + c] = o1;
            }
        }
    }
}

// ---------------------------------------------------------------------------
// RoPE in-place on Q and K (fp32).
// ---------------------------------------------------------------------------
__global__ __launch_bounds__(64) void rope_kernel(float* __restrict__ qkv)
{
    int s = blockIdx.x;
    int d = threadIdx.x;
    double inv = pow(50000.0, -2.0 * (double)d / 128.0);
    double ang = (double)s * inv;
    float c  = (float)cos(ang);
    float sn = (float)sin(ang);

    float* row = qkv + (size_t)s * QKV_N;
#pragma unroll 1
    for (int h = 0; h < NH + NG; h++) {
        float* base = (h < NH) ? (row + h * HD)
                               : (row + MODEL_DIM + (h - NH) * HD);
        float x1 = base[d];
        float x2 = base[d + 64];
        base[d]      = x1 * c - x2 * sn;
        base[d + 64] = x2 * c + x1 * sn;
    }
}

// ---------------------------------------------------------------------------
// bf16x3 mma.sync flash attention (identical to R3; fp32 output).
// ---------------------------------------------------------------------------
#define AQ_STRIDE 136
#define AP_STRIDE 72
#define OFF_QHI 0
#define OFF_QLO (OFF_QHI + 128 * AQ_STRIDE)
#define OFF_KHI (OFF_QLO + 128 * AQ_STRIDE)
#define OFF_KLO (OFF_KHI + 64 * AQ_STRIDE)
#define OFF_VHI (OFF_KLO + 64 * AQ_STRIDE)
#define OFF_VLO (OFF_VHI + 64 * AQ_STRIDE)
#define OFF_PHI (OFF_VLO + 64 * AQ_STRIDE)
#define OFF_PLO (OFF_PHI + 128 * AP_STRIDE)
#define ATTN_SMEM_BYTES ((OFF_PLO + 128 * AP_STRIDE) * 2)

#define LDSM4(R0,R1,R2,R3,ADDR) \
    asm volatile("ldmatrix.sync.aligned.m8n8.x4.shared.b16 {%0,%1,%2,%3}, [%4];" \
                 : "=r"(R0),"=r"(R1),"=r"(R2),"=r"(R3) : "r"(ADDR))
#define LDSM4T(R0,R1,R2,R3,ADDR) \
    asm volatile("ldmatrix.sync.aligned.m8n8.x4.trans.shared.b16 {%0,%1,%2,%3}, [%4];" \
                 : "=r"(R0),"=r"(R1),"=r"(R2),"=r"(R3) : "r"(ADDR))

__device__ __forceinline__ void mma_bf16(float c[4],
                                         uint32_t a0, uint32_t a1, uint32_t a2, uint32_t a3,
                                         uint32_t b0, uint32_t b1) {
    asm volatile(
        "mma.sync.aligned.m16n8k16.row.col.f32.bf16.bf16.f32 "
        "{%0,%1,%2,%3}, {%4,%5,%6,%7}, {%8,%9}, {%0,%1,%2,%3};\n"
        : "+f"(c[0]), "+f"(c[1]), "+f"(c[2]), "+f"(c[3])
        : "r"(a0), "r"(a1), "r"(a2), "r"(a3), "r"(b0), "r"(b1));
}

__device__ __forceinline__ void split_bf16(float x, __nv_bfloat16& hi, __nv_bfloat16& lo) {
    hi = __float2bfloat16(x);
    lo = __float2bfloat16(x - __bfloat162float(hi));
}

__global__ __launch_bounds__(256) void attn_mma_kernel(
    const float* __restrict__ qkv, float* __restrict__ out)
{
    extern __shared__ __nv_bfloat16 sbm[];
    __nv_bfloat16* Qhi = sbm + OFF_QHI;
    __nv_bfloat16* Qlo = sbm + OFF_QLO;
    __nv_bfloat16* Khi = sbm + OFF_KHI;
    __nv_bfloat16* Klo = sbm + OFF_KLO;
    __nv_bfloat16* Vhi = sbm + OFF_VHI;
    __nv_bfloat16* Vlo = sbm + OFF_VLO;
    __nv_bfloat16* Phi = sbm + OFF_PHI;
    __nv_bfloat16* Plo = sbm + OFF_PLO;

    const int tid  = threadIdx.x;
    const int warp = tid >> 5;
    const int lane = tid & 31;
    const int mb = (gridDim.x - 1) - blockIdx.x;
    const int h  = blockIdx.y;
    const int kvh = h >> 2;
    const int m0 = mb * 128;
    const float scale = 0.08838834764831843f;

#pragma unroll
    for (int t = 0; t < 16; t++) {
        int idx = tid + t * 256;
        int r  = idx >> 5;
        int c  = (idx & 31) * 4;
        float4 v = *(const float4*)&qkv[(size_t)(m0 + r) * QKV_N + h * HD + c];
        v.x *= scale; v.y *= scale; v.z *= scale; v.w *= scale;
        __nv_bfloat16 h0,h1,h2,h3,l0,l1,l2,l3;
        split_bf16(v.x,h0,l0); split_bf16(v.y,h1,l1);
        split_bf16(v.z,h2,l2); split_bf16(v.w,h3,l3);
        int o = r * AQ_STRIDE + c;
        *(__nv_bfloat162*)&Qhi[o]   = __nv_bfloat162{h0,h1};
        *(__nv_bfloat162*)&Qhi[o+2] = __nv_bfloat162{h2,h3};
        *(__nv_bfloat162*)&Qlo[o]   = __nv_bfloat162{l0,l1};
        *(__nv_bfloat162*)&Qlo[o+2] = __nv_bfloat162{l2,l3};
    }

    float mrow[2] = {-1e30f, -1e30f};
    float lrow[2] = {0.f, 0.f};
    float oacc[16][4];
#pragma unroll
    for (int nt = 0; nt < 16; nt++)
#pragma unroll
        for (int e = 0; e < 4; e++) oacc[nt][e] = 0.f;

    const int row0g = m0 + warp * 16 + (lane >> 2);
    const int row1g = row0g + 8;

    const int nkb = 2 * mb + 2;
    for (int kb = 0; kb < nkb; kb++) {
        const int k0 = kb * 64;
        __syncthreads();

#pragma unroll
        for (int t = 0; t < 8; t++) {
            int idx = tid + t * 256;
            int r  = idx >> 5;
            int c  = (idx & 31) * 4;
            size_t base = (size_t)(k0 + r) * QKV_N + MODEL_DIM + kvh * HD + c;
            float4 kv = *(const float4*)&qkv[base];
            float4 vv = *(const float4*)&qkv[base + KV_DIM];
            int o = r * AQ_STRIDE + c;
            __nv_bfloat16 h0,h1,h2,h3,l0,l1,l2,l3;
            split_bf16(kv.x,h0,l0); split_bf16(kv.y,h1,l1);
            split_bf16(kv.z,h2,l2); split_bf16(kv.w,h3,l3);
            *(__nv_bfloat162*)&Khi[o]   = __nv_bfloat162{h0,h1};
            *(__nv_bfloat162*)&Khi[o+2] = __nv_bfloat162{h2,h3};
            *(__nv_bfloat162*)&Klo[o]   = __nv_bfloat162{l0,l1};
            *(__nv_bfloat162*)&Klo[o+2] = __nv_bfloat162{l2,l3};
            split_bf16(vv.x,h0,l0); split_bf16(vv.y,h1,l1);
            split_bf16(vv.z,h2,l2); split_bf16(vv.w,h3,l3);
            *(__nv_bfloat162*)&Vhi[o]   = __nv_bfloat162{h0,h1};
            *(__nv_bfloat162*)&Vhi[o+2] = __nv_bfloat162{h2,h3};
            *(__nv_bfloat162*)&Vlo[o]   = __nv_bfloat162{l0,l1};
            *(__nv_bfloat162*)&Vlo[o+2] = __nv_bfloat162{l2,l3};
        }
        __syncthreads();

        float sacc[8][4];
#pragma unroll
        for (int nt = 0; nt < 8; nt++)
#pragma unroll
            for (int e = 0; e < 4; e++) sacc[nt][e] = 0.f;

        const int a_row = warp * 16 + (lane & 15);
        const int a_col8 = (lane >> 4) * 8;

#pragma unroll
        for (int ks = 0; ks < 8; ks++) {
            uint32_t ah[4], al[4];
            {
                uint32_t ad = (uint32_t)__cvta_generic_to_shared(
                    &Qhi[a_row * AQ_STRIDE + ks * 16 + a_col8]);
                LDSM4(ah[0], ah[1], ah[2], ah[3], ad);
                ad = (uint32_t)__cvta_generic_to_shared(
                    &Qlo[a_row * AQ_STRIDE + ks * 16 + a_col8]);
                LDSM4(al[0], al[1], al[2], al[3], ad);
            }
#pragma unroll
            for (int ng = 0; ng < 4; ng++) {
                uint32_t bh[4], bl[4];
                uint32_t bd = (uint32_t)__cvta_generic_to_shared(
                    &Khi[(ng * 16 + (lane & 15)) * AQ_STRIDE + ks * 16 + a_col8]);
                LDSM4(bh[0], bh[1], bh[2], bh[3], bd);
                bd = (uint32_t)__cvta_generic_to_shared(
                    &Klo[(ng * 16 + (lane & 15)) * AQ_STRIDE + ks * 16 + a_col8]);
                LDSM4(bl[0], bl[1], bl[2], bl[3], bd);
                int nt = ng * 2;
                mma_bf16(sacc[nt],   ah[0],ah[1],ah[2],ah[3], bh[0],bh[2]);
                mma_bf16(sacc[nt],   ah[0],ah[1],ah[2],ah[3], bl[0],bl[2]);
                mma_bf16(sacc[nt],   al[0],al[1],al[2],al[3], bh[0],bh[2]);
                mma_bf16(sacc[nt+1], ah[0],ah[1],ah[2],ah[3], bh[1],bh[3]);
                mma_bf16(sacc[nt+1], ah[0],ah[1],ah[2],ah[3], bl[1],bl[3]);
                mma_bf16(sacc[nt+1], al[0],al[1],al[2],al[3], bh[1],bh[3]);
            }
        }

        if (k0 + 63 > m0) {
#pragma unroll
            for (int nt = 0; nt < 8; nt++) {
                int c = k0 + nt * 8 + 2 * (lane & 3);
                if (c     > row0g) sacc[nt][0] = -1e30f;
                if (c + 1 > row0g) sacc[nt][1] = -1e30f;
                if (c     > row1g) sacc[nt][2] = -1e30f;
                if (c + 1 > row1g) sacc[nt][3] = -1e30f;
            }
        }

        float mx0 = -1e30f, mx1 = -1e30f;
#pragma unroll
        for (int nt = 0; nt < 8; nt++) {
            mx0 = fmaxf(mx0, fmaxf(sacc[nt][0], sacc[nt][1]));
            mx1 = fmaxf(mx1, fmaxf(sacc[nt][2], sacc[nt][3]));
        }
        mx0 = fmaxf(mx0, __shfl_xor_sync(0xffffffffu, mx0, 1));
        mx0 = fmaxf(mx0, __shfl_xor_sync(0xffffffffu, mx0, 2));
        mx1 = fmaxf(mx1, __shfl_xor_sync(0xffffffffu, mx1, 1));
        mx1 = fmaxf(mx1, __shfl_xor_sync(0xffffffffu, mx1, 2));

        float mn0 = fmaxf(mrow[0], mx0);
        float mn1 = fmaxf(mrow[1], mx1);
        float al0 = __expf(mrow[0] - mn0);
        float al1 = __expf(mrow[1] - mn1);

        const int prl0 = warp * 16 + (lane >> 2);
        float s0 = 0.f, s1 = 0.f;
#pragma unroll
        for (int nt = 0; nt < 8; nt++) {
            int col = nt * 8 + 2 * (lane & 3);
            float p00 = __expf(sacc[nt][0] - mn0);
            float p01 = __expf(sacc[nt][1] - mn0);
            float p10 = __expf(sacc[nt][2] - mn1);
            float p11 = __expf(sacc[nt][3] - mn1);
            s0 += p00 + p01;
            s1 += p10 + p11;
            __nv_bfloat16 h0,h1,l0,l1;
            split_bf16(p00,h0,l0); split_bf16(p01,h1,l1);
            *(__nv_bfloat162*)&Phi[prl0 * AP_STRIDE + col] = __nv_bfloat162{h0,h1};
            *(__nv_bfloat162*)&Plo[prl0 * AP_STRIDE + col] = __nv_bfloat162{l0,l1};
            split_bf16(p10,h0,l0); split_bf16(p11,h1,l1);
            *(__nv_bfloat162*)&Phi[(prl0+8) * AP_STRIDE + col] = __nv_bfloat162{h0,h1};
            *(__nv_bfloat162*)&Plo[(prl0+8) * AP_STRIDE + col] = __nv_bfloat162{l0,l1};
        }
        s0 += __shfl_xor_sync(0xffffffffu, s0, 1);
        s0 += __shfl_xor_sync(0xffffffffu, s0, 2);
        s1 += __shfl_xor_sync(0xffffffffu, s1, 1);
        s1 += __shfl_xor_sync(0xffffffffu, s1, 2);

        lrow[0] = lrow[0] * al0 + s0;
        lrow[1] = lrow[1] * al1 + s1;
        mrow[0] = mn0;
        mrow[1] = mn1;
#pragma unroll
        for (int nt = 0; nt < 16; nt++) {
            oacc[nt][0] *= al0; oacc[nt][1] *= al0;
            oacc[nt][2] *= al1; oacc[nt][3] *= al1;
        }
        __syncwarp();

        const int v_row = (lane & 7) + 8 * ((lane >> 3) & 1);
        const int v_col8 = 8 * (lane >> 4);
#pragma unroll
        for (int ks = 0; ks < 4; ks++) {
            int kk = ks * 16;
            uint32_t ph4[4], pl4[4];
            uint32_t ad = (uint32_t)__cvta_generic_to_shared(
                &Phi[(warp * 16 + (lane & 15)) * AP_STRIDE + kk + a_col8]);
            LDSM4(ph4[0], ph4[1], ph4[2], ph4[3], ad);
            ad = (uint32_t)__cvta_generic_to_shared(
                &Plo[(warp * 16 + (lane & 15)) * AP_STRIDE + kk + a_col8]);
            LDSM4(pl4[0], pl4[1], pl4[2], pl4[3], ad);
#pragma unroll
            for (int dg = 0; dg < 8; dg++) {
                int db = dg * 16;
                uint32_t vh[4], vl[4];
                uint32_t vd = (uint32_t)__cvta_generic_to_shared(
                    &Vhi[(kk + v_row) * AQ_STRIDE + db + v_col8]);
                LDSM4T(vh[0], vh[1], vh[2], vh[3], vd);
                vd = (uint32_t)__cvta_generic_to_shared(
                    &Vlo[(kk + v_row) * AQ_STRIDE + db + v_col8]);
                LDSM4T(vl[0], vl[1], vl[2], vl[3], vd);
                int nt = dg * 2;
                mma_bf16(oacc[nt],   ph4[0],ph4[1],ph4[2],ph4[3], vh[0],vh[1]);
                mma_bf16(oacc[nt],   ph4[0],ph4[1],ph4[2],ph4[3], vl[0],vl[1]);
                mma_bf16(oacc[nt],   pl4[0],pl4[1],pl4[2],pl4[3], vh[0],vh[1]);
                mma_bf16(oacc[nt+1], ph4[0],ph4[1],ph4[2],ph4[3], vh[2],vh[3]);
                mma_bf16(oacc[nt+1], ph4[0],ph4[1],ph4[2],ph4[3], vl[2],vl[3]);
                mma_bf16(oacc[nt+1], pl4[0],pl4[1],pl4[2],pl4[3], vh[2],vh[3]);
            }
        }
        __syncwarp();
    }

    float inv0 = 1.f / lrow[0];
    float inv1 = 1.f / lrow[1];
#pragma unroll
    for (int nt = 0; nt < 16; nt++) {
        int d = nt * 8 + 2 * (lane & 3);
        size_t b0 = (size_t)row0g * MODEL_DIM + h * HD + d;
        size_t b1 = (size_t)row1g * MODEL_DIM + h * HD + d;
        *(float2*)&out[b0] = float2{oacc[nt][0] * inv0, oacc[nt][1] * inv0};
        *(float2*)&out[b1] = float2{oacc[nt][2] * inv1, oacc[nt][3] * inv1};
    }
}

// ---------------------------------------------------------------------------
extern "C" void kernel_launch(void* const* d_in, const int* in_sizes, int n_in,
                              void* d_out, int out_size)
{
    const float* x    = (const float*)d_in[0];
    const float* Wqkv = (const float*)d_in[1];
    const float* bqkv = (const float*)d_in[2];
    const float* Wo   = (const float*)d_in[3];
    const float* bo   = (const float*)d_in[4];
    float* out = (float*)d_out;

    float *qkv_ptr, *attn_ptr;
    float4 *xpk, *apk, *wqpk, *wopk;
    cudaGetSymbolAddress((void**)&qkv_ptr, g_qkv);
    cudaGetSymbolAddress((void**)&attn_ptr, g_attn);
    cudaGetSymbolAddress((void**)&xpk, g_xpk);
    cudaGetSymbolAddress((void**)&apk, g_apk);
    cudaGetSymbolAddress((void**)&wqpk, g_wqkvpk);
    cudaGetSymbolAddress((void**)&wopk, g_wopk);

    cudaFuncSetAttribute(gemm_pk_kernel,
                         cudaFuncAttributeMaxDynamicSharedMemorySize, GEMM_SMEM);
    cudaFuncSetAttribute(attn_mma_kernel,
                         cudaFuncAttributeMaxDynamicSharedMemorySize, ATTN_SMEM_BYTES);

    // 0) pack operands (tf32-rounded, fragment order)
    pack_a_kernel<<<dim3(MODEL_DIM / 8 / 8, S_LEN / 16), 256>>>(x, xpk, S_LEN, MODEL_DIM);
    pack_b_kernel<<<dim3(MODEL_DIM / 8 / 8, QKV_N / 16), 256>>>(Wqkv, wqpk, MODEL_DIM, QKV_N);
    pack_b_kernel<<<dim3(MODEL_DIM / 8 / 8, MODEL_DIM / 16), 256>>>(Wo, wopk, MODEL_DIM, MODEL_DIM);

    // 1) QKV projection
    gemm_pk_kernel<<<dim3(QKV_N / 128, S_LEN / 128), 256, GEMM_SMEM>>>(
        xpk, wqpk, bqkv, qkv_ptr, S_LEN, QKV_N, MODEL_DIM);

    // 2) RoPE (fp32, in place)
    rope_kernel<<<S_LEN, 64>>>(qkv_ptr);

    // 3) attention (bf16x3 mma.sync) -> fp32
    attn_mma_kernel<<<dim3(S_LEN / 128, NH), 256, ATTN_SMEM_BYTES>>>(qkv_ptr, attn_ptr);

    // 4) pack attention output, then output projection
    pack_a_kernel<<<dim3(MODEL_DIM / 8 / 8, S_LEN / 16), 256>>>(attn_ptr, apk, S_LEN, MODEL_DIM);
    gemm_pk_kernel<<<dim3(MODEL_DIM / 128, S_LEN / 128), 256, GEMM_SMEM>>>(
        apk, wopk, bo, out, S_LEN, MODEL_DIM, MODEL_DIM);
}